// round 1
// baseline (speedup 1.0000x reference)
#include <cuda_runtime.h>
#include <cstdint>

// ---------------------------------------------------------------------------
// CrystalGraphConvolution: 3 message-passing steps.
//   merged = [x[src], x[dst], e]            (per edge, 320 wide)
//   s = merged @ Ks + bs ; g = merged @ Kg + bg
//   msg = sigmoid(s) * softplus(g)
//   agg = segment_sum(msg, src)
//   x   = softplus(x + agg)
//
// Reorganization:
//   P = x @ W_node   where W_node cols = [Ks_src | Kg_src | Ks_dst | Kg_dst]
//       (50000 x 512)   -> per edge: row[src][0:256], row[dst][256:512]
//   E = e @ W_edge + bias_e  (step-invariant, precomputed once)
//       W_edge cols = [Ks_edge | Kg_edge], bias_e = [bs | bg]   (800000 x 256)
//   edge kernel: s/g = P-parts + E-parts, msg, red.v4 atomic into agg[src]
// ---------------------------------------------------------------------------

#define MAX_NODES 50000
#define MAX_EDGES 800000

static __device__ float g_E[(size_t)MAX_EDGES * 256];   // ~819 MB
static __device__ float g_P[(size_t)MAX_NODES * 512];   // ~102 MB
static __device__ float g_agg[(size_t)MAX_NODES * 128];
static __device__ float g_x[(size_t)MAX_NODES * 128];
static __device__ float g_Wn[128 * 512];
static __device__ float g_We[64 * 256];
static __device__ float g_be[256];

// ---------------------------------------------------------------------------
__device__ __forceinline__ float fast_sigmoid(float x) {
    return __fdividef(1.0f, 1.0f + __expf(-x));
}
__device__ __forceinline__ float fast_softplus(float x) {
    // stable: max(x,0) + log(1 + exp(-|x|))
    return fmaxf(x, 0.0f) + __logf(1.0f + __expf(-fabsf(x)));
}

// ---------------------------------------------------------------------------
// Pack weights: kernel_s/kernel_g are [320,128] row-major.
__global__ void repack_kernel(const float* __restrict__ ks, const float* __restrict__ kg,
                              const float* __restrict__ bs, const float* __restrict__ bg) {
    int i = blockIdx.x * blockDim.x + threadIdx.x;
    if (i < 128 * 512) {
        int k = i >> 9, c = i & 511;
        float v;
        if (c < 128)      v = ks[k * 128 + c];             // src -> s
        else if (c < 256) v = kg[k * 128 + (c - 128)];     // src -> g
        else if (c < 384) v = ks[(128 + k) * 128 + (c - 256)]; // dst -> s
        else              v = kg[(128 + k) * 128 + (c - 384)]; // dst -> g
        g_Wn[i] = v;
    }
    if (i < 64 * 256) {
        int k = i >> 8, c = i & 255;
        g_We[i] = (c < 128) ? ks[(256 + k) * 128 + c] : kg[(256 + k) * 128 + (c - 128)];
    }
    if (i < 256) g_be[i] = (i < 128) ? bs[i] : bg[i - 128];
}

// ---------------------------------------------------------------------------
// Tiled fp32 GEMM: C[M,N] = A[M,K] @ B[K,N] (+ bias[N]).
// BM=BN=128, BK=8, 256 threads, 8x8 per thread. Requires N%128==0, K%8==0.
__global__ __launch_bounds__(256) void sgemm_tile(
    const float* __restrict__ A, const float* __restrict__ B,
    const float* __restrict__ bias, float* __restrict__ C,
    int M, int N, int K)
{
    __shared__ float As[8][128];
    __shared__ float Bs[8][128];

    const int m0 = blockIdx.y * 128;
    const int n0 = blockIdx.x * 128;
    const int tid = threadIdx.x;
    const int tr = tid >> 4;        // 0..15
    const int tc = tid & 15;        // 0..15

    const int arow = tid >> 1;          // 0..127
    const int acol = (tid & 1) * 4;     // 0 or 4
    const int brow = tid >> 5;          // 0..7
    const int bcol = (tid & 31) * 4;    // 0..124

    const bool avalid = (m0 + arow) < M;
    const float* Aptr = A + (size_t)(m0 + arow) * K + acol;

    float acc[8][8];
#pragma unroll
    for (int i = 0; i < 8; i++)
#pragma unroll
        for (int j = 0; j < 8; j++) acc[i][j] = 0.0f;

    for (int kk = 0; kk < K; kk += 8) {
        float4 av = avalid ? *(const float4*)(Aptr + kk) : make_float4(0.f, 0.f, 0.f, 0.f);
        As[acol + 0][arow] = av.x;
        As[acol + 1][arow] = av.y;
        As[acol + 2][arow] = av.z;
        As[acol + 3][arow] = av.w;
        *(float4*)&Bs[brow][bcol] =
            *(const float4*)(B + (size_t)(kk + brow) * N + n0 + bcol);
        __syncthreads();

#pragma unroll
        for (int k = 0; k < 8; k++) {
            float a[8], b[8];
#pragma unroll
            for (int i = 0; i < 8; i++) a[i] = As[k][tr * 8 + i];
#pragma unroll
            for (int j = 0; j < 8; j++) b[j] = Bs[k][tc * 8 + j];
#pragma unroll
            for (int i = 0; i < 8; i++)
#pragma unroll
                for (int j = 0; j < 8; j++) acc[i][j] = fmaf(a[i], b[j], acc[i][j]);
        }
        __syncthreads();
    }

    float bv[8];
#pragma unroll
    for (int j = 0; j < 8; j++) bv[j] = bias ? bias[n0 + tc * 8 + j] : 0.0f;

#pragma unroll
    for (int i = 0; i < 8; i++) {
        int row = m0 + tr * 8 + i;
        if (row < M) {
            float* crow = C + (size_t)row * N + n0 + tc * 8;
#pragma unroll
            for (int j = 0; j < 8; j++) crow[j] = acc[i][j] + bv[j];
        }
    }
}

// ---------------------------------------------------------------------------
// One warp per edge. Lane l owns columns 4l..4l+3 (128 cols / warp).
__global__ __launch_bounds__(256) void edge_kernel(
    const float* __restrict__ P, const float* __restrict__ E,
    const int* __restrict__ pair, float* __restrict__ agg, int n_edges)
{
    int gw = (blockIdx.x * blockDim.x + threadIdx.x) >> 5;
    int lane = threadIdx.x & 31;
    if (gw >= n_edges) return;

    int src = pair[2 * gw];
    int dst = pair[2 * gw + 1];

    const float4* ps = (const float4*)(P + (size_t)src * 512);        // [s_src | g_src]
    const float4* pd = (const float4*)(P + (size_t)dst * 512 + 256);  // [s_dst | g_dst]
    const float4* ep = (const float4*)(E + (size_t)gw * 256);         // [e_s | e_g]

    float4 ss = ps[lane];
    float4 gs = ps[lane + 32];
    float4 sd = pd[lane];
    float4 gd = pd[lane + 32];
    float4 es = ep[lane];
    float4 eg = ep[lane + 32];

    float s0 = ss.x + sd.x + es.x, g0 = gs.x + gd.x + eg.x;
    float s1 = ss.y + sd.y + es.y, g1 = gs.y + gd.y + eg.y;
    float s2 = ss.z + sd.z + es.z, g2 = gs.z + gd.z + eg.z;
    float s3 = ss.w + sd.w + es.w, g3 = gs.w + gd.w + eg.w;

    float m0 = fast_sigmoid(s0) * fast_softplus(g0);
    float m1 = fast_sigmoid(s1) * fast_softplus(g1);
    float m2 = fast_sigmoid(s2) * fast_softplus(g2);
    float m3 = fast_sigmoid(s3) * fast_softplus(g3);

    float* dp = agg + (size_t)src * 128 + lane * 4;
    asm volatile("red.global.add.v4.f32 [%0], {%1,%2,%3,%4};"
                 :: "l"(dp), "f"(m0), "f"(m1), "f"(m2), "f"(m3)
                 : "memory");
}

// ---------------------------------------------------------------------------
__global__ void zero_kernel(float* __restrict__ p, int n) {
    int i = blockIdx.x * blockDim.x + threadIdx.x;
    if (i < n) p[i] = 0.0f;
}

__global__ void update_kernel(const float* __restrict__ xin, const float* __restrict__ agg,
                              float* __restrict__ xout, int n) {
    int i = blockIdx.x * blockDim.x + threadIdx.x;
    if (i < n) xout[i] = fast_softplus(xin[i] + agg[i]);
}

// ---------------------------------------------------------------------------
extern "C" void kernel_launch(void* const* d_in, const int* in_sizes, int n_in,
                              void* d_out, int out_size) {
    const float* atom = (const float*)d_in[0];   // [n_nodes, 128]
    const float* esph = (const float*)d_in[1];   // [n_edges, 64]
    const float* ks   = (const float*)d_in[3];   // [320, 128]
    const float* bs   = (const float*)d_in[4];   // [128]
    const float* kg   = (const float*)d_in[5];   // [320, 128]
    const float* bg   = (const float*)d_in[6];   // [128]
    const int*   pair = (const int*)d_in[7];     // [n_edges, 2] int32
    float* out = (float*)d_out;

    const int n_nodes = in_sizes[0] / 128;
    const int n_edges = in_sizes[1] / 64;

    float *pE, *pP, *pAgg, *pX, *pWn, *pWe, *pBe;
    cudaGetSymbolAddress((void**)&pE, g_E);
    cudaGetSymbolAddress((void**)&pP, g_P);
    cudaGetSymbolAddress((void**)&pAgg, g_agg);
    cudaGetSymbolAddress((void**)&pX, g_x);
    cudaGetSymbolAddress((void**)&pWn, g_Wn);
    cudaGetSymbolAddress((void**)&pWe, g_We);
    cudaGetSymbolAddress((void**)&pBe, g_be);

    // 1. pack weights
    repack_kernel<<<256, 256>>>(ks, kg, bs, bg);

    // 2. precompute edge term E = esph @ W_edge + bias_e   (M=n_edges, N=256, K=64)
    {
        dim3 grid(256 / 128, (n_edges + 127) / 128);
        sgemm_tile<<<grid, 256>>>(esph, pWe, pBe, pE, n_edges, 256, 64);
    }

    const float* xin = atom;
    const int nelem = n_nodes * 128;
    for (int step = 0; step < 3; step++) {
        zero_kernel<<<(nelem + 511) / 512, 512>>>(pAgg, nelem);

        // P = x @ W_node   (M=n_nodes, N=512, K=128)
        dim3 gn(512 / 128, (n_nodes + 127) / 128);
        sgemm_tile<<<gn, 256>>>(xin, pWn, nullptr, pP, n_nodes, 512, 128);

        edge_kernel<<<(n_edges + 7) / 8, 256>>>(pP, pE, pair, pAgg, n_edges);

        float* xout = (step == 2) ? out : pX;
        update_kernel<<<(nelem + 255) / 256, 256>>>(xin, pAgg, xout, nelem);
        xin = pX;
    }
}

// round 2
// speedup vs baseline: 1.6460x; 1.6460x over previous
#include <cuda_runtime.h>
#include <cuda_fp16.h>
#include <cstdint>

// ---------------------------------------------------------------------------
// CrystalGraphConvolution, restructured:
//   P = x @ W_node  -> fp16, columns interleaved (s,g) pairs:
//       row layout: [ (s_src,g_src) x128 | (s_dst,g_dst) x128 ]  (512 halves)
//   E = e @ W_edge + bias -> fp16, interleaved (s,g) pairs (256 halves), step-invariant
//   edge kernel: 1 warp/edge, 3x uint4 loads per lane, fused sigmoid*softplus,
//                red.global.add.v4.f32 into agg[src]
//   x = softplus(x + agg)
// ---------------------------------------------------------------------------

#define MAX_NODES 50000
#define MAX_EDGES 800000

static __device__ __align__(16) __half g_E[(size_t)MAX_EDGES * 256];  // ~410 MB
static __device__ __align__(16) __half g_P[(size_t)MAX_NODES * 512];  // ~51 MB
static __device__ float g_agg[(size_t)MAX_NODES * 128];
static __device__ float g_x[(size_t)MAX_NODES * 128];
static __device__ float g_Wn[128 * 512];
static __device__ float g_We[64 * 256];
static __device__ float g_be[256];

__device__ __forceinline__ float fast_sigmoid(float x) {
    return __fdividef(1.0f, 1.0f + __expf(-x));
}
__device__ __forceinline__ float fast_softplus(float x) {
    return fmaxf(x, 0.0f) + __logf(1.0f + __expf(-fabsf(x)));
}

// ---------------------------------------------------------------------------
// Repack weights into interleaved (s,g) column order.
// kernel_s / kernel_g are [320,128] row-major.
__global__ void repack_kernel(const float* __restrict__ ks, const float* __restrict__ kg,
                              const float* __restrict__ bs, const float* __restrict__ bg) {
    int i = blockIdx.x * blockDim.x + threadIdx.x;
    if (i < 128 * 512) {
        int k = i >> 9, j = i & 511;
        float v;
        if (j < 256) {
            int c = j >> 1;
            v = (j & 1) ? kg[k * 128 + c] : ks[k * 128 + c];          // src block
        } else {
            int c = (j - 256) >> 1;
            v = (j & 1) ? kg[(128 + k) * 128 + c] : ks[(128 + k) * 128 + c]; // dst block
        }
        g_Wn[i] = v;
    }
    if (i < 64 * 256) {
        int k = i >> 8, j = i & 255;
        int c = j >> 1;
        g_We[i] = (j & 1) ? kg[(256 + k) * 128 + c] : ks[(256 + k) * 128 + c];
    }
    if (i < 256) {
        int c = i >> 1;
        g_be[i] = (i & 1) ? bg[c] : bs[c];
    }
}

// ---------------------------------------------------------------------------
// fp32 GEMM -> fp16 out. C[M,N] = A[M,K] @ B[K,N] (+bias). BM=BN=128, BK=16,
// 256 threads, 8x8/thread, double-buffered smem with register-staged prefetch.
// Requires N%128==0, K%16==0.
__global__ __launch_bounds__(256) void sgemm_h(
    const float* __restrict__ A, const float* __restrict__ B,
    const float* __restrict__ bias, __half* __restrict__ C,
    int M, int N, int K)
{
    __shared__ float As[2][16][128];
    __shared__ float Bs[2][16][128];

    const int m0 = blockIdx.y * 128;
    const int n0 = blockIdx.x * 128;
    const int tid = threadIdx.x;
    const int tr = tid >> 4;   // 0..15
    const int tc = tid & 15;   // 0..15

    // A loader: float4 ids {tid, tid+256}; row=f>>2, kcol=(f&3)*4
    const int ar0 = tid >> 2;
    const int ak  = (tid & 3) * 4;
    const int ar1 = ar0 + 64;
    // B loader: float4 ids {tid, tid+256}; row=f>>5, ncol=(f&31)*4
    const int br  = tid >> 5;
    const int bn  = (tid & 31) * 4;

    const bool av0 = (m0 + ar0) < M;
    const bool av1 = (m0 + ar1) < M;
    const float* Ap0 = A + (size_t)(m0 + ar0) * K + ak;
    const float* Ap1 = A + (size_t)(m0 + ar1) * K + ak;
    const float* Bp0 = B + (size_t)br * N + n0 + bn;
    const float* Bp1 = B + (size_t)(br + 8) * N + n0 + bn;

    const float4 z = make_float4(0.f, 0.f, 0.f, 0.f);

    // --- prologue: tile kk=0 into buf 0
    float4 a0 = av0 ? *(const float4*)(Ap0) : z;
    float4 a1 = av1 ? *(const float4*)(Ap1) : z;
    float4 b0 = *(const float4*)(Bp0);
    float4 b1 = *(const float4*)(Bp1);
    As[0][ak + 0][ar0] = a0.x; As[0][ak + 1][ar0] = a0.y;
    As[0][ak + 2][ar0] = a0.z; As[0][ak + 3][ar0] = a0.w;
    As[0][ak + 0][ar1] = a1.x; As[0][ak + 1][ar1] = a1.y;
    As[0][ak + 2][ar1] = a1.z; As[0][ak + 3][ar1] = a1.w;
    *(float4*)&Bs[0][br][bn]     = b0;
    *(float4*)&Bs[0][br + 8][bn] = b1;
    __syncthreads();

    float acc[8][8];
#pragma unroll
    for (int i = 0; i < 8; i++)
#pragma unroll
        for (int j = 0; j < 8; j++) acc[i][j] = 0.0f;

    int buf = 0;
    for (int kk = 16; kk < K; kk += 16) {
        // prefetch next tile to regs
        a0 = av0 ? *(const float4*)(Ap0 + kk) : z;
        a1 = av1 ? *(const float4*)(Ap1 + kk) : z;
        b0 = *(const float4*)(Bp0 + (size_t)kk * N);
        b1 = *(const float4*)(Bp1 + (size_t)kk * N);

#pragma unroll
        for (int k = 0; k < 16; k++) {
            float av[8], bv[8];
            *(float4*)&av[0] = *(const float4*)&As[buf][k][tr * 8];
            *(float4*)&av[4] = *(const float4*)&As[buf][k][tr * 8 + 4];
            *(float4*)&bv[0] = *(const float4*)&Bs[buf][k][tc * 8];
            *(float4*)&bv[4] = *(const float4*)&Bs[buf][k][tc * 8 + 4];
#pragma unroll
            for (int i = 0; i < 8; i++)
#pragma unroll
                for (int j = 0; j < 8; j++) acc[i][j] = fmaf(av[i], bv[j], acc[i][j]);
        }

        int nb = buf ^ 1;
        As[nb][ak + 0][ar0] = a0.x; As[nb][ak + 1][ar0] = a0.y;
        As[nb][ak + 2][ar0] = a0.z; As[nb][ak + 3][ar0] = a0.w;
        As[nb][ak + 0][ar1] = a1.x; As[nb][ak + 1][ar1] = a1.y;
        As[nb][ak + 2][ar1] = a1.z; As[nb][ak + 3][ar1] = a1.w;
        *(float4*)&Bs[nb][br][bn]     = b0;
        *(float4*)&Bs[nb][br + 8][bn] = b1;
        __syncthreads();
        buf = nb;
    }

    // last tile
#pragma unroll
    for (int k = 0; k < 16; k++) {
        float av[8], bv[8];
        *(float4*)&av[0] = *(const float4*)&As[buf][k][tr * 8];
        *(float4*)&av[4] = *(const float4*)&As[buf][k][tr * 8 + 4];
        *(float4*)&bv[0] = *(const float4*)&Bs[buf][k][tc * 8];
        *(float4*)&bv[4] = *(const float4*)&Bs[buf][k][tc * 8 + 4];
#pragma unroll
        for (int i = 0; i < 8; i++)
#pragma unroll
            for (int j = 0; j < 8; j++) acc[i][j] = fmaf(av[i], bv[j], acc[i][j]);
    }

    float bv8[8];
#pragma unroll
    for (int j = 0; j < 8; j++) bv8[j] = bias ? bias[n0 + tc * 8 + j] : 0.0f;

#pragma unroll
    for (int i = 0; i < 8; i++) {
        int row = m0 + tr * 8 + i;
        if (row < M) {
            __half hv[8];
#pragma unroll
            for (int j = 0; j < 8; j++) hv[j] = __float2half(acc[i][j] + bv8[j]);
            *(uint4*)(C + (size_t)row * N + n0 + tc * 8) = *(uint4*)hv;
        }
    }
}

// ---------------------------------------------------------------------------
// One warp per edge; lane l owns output cols 4l..4l+3.
// P row: [ (s,g)x128 src | (s,g)x128 dst ], E row: (s,g)x128.
__global__ __launch_bounds__(256) void edge_kernel(
    const __half* __restrict__ P, const __half* __restrict__ E,
    const int* __restrict__ pair, float* __restrict__ agg, int n_edges)
{
    int gw = (blockIdx.x * blockDim.x + threadIdx.x) >> 5;
    int lane = threadIdx.x & 31;
    if (gw >= n_edges) return;

    int src = pair[2 * gw];
    int dst = pair[2 * gw + 1];

    const uint4* ps = (const uint4*)(P + (size_t)src * 512);
    const uint4* pd = (const uint4*)(P + (size_t)dst * 512 + 256);
    const uint4* ep = (const uint4*)(E + (size_t)gw * 256);

    uint4 a = ps[lane];
    uint4 b = pd[lane];
    uint4 e = ep[lane];

    float m[4];
#pragma unroll
    for (int i = 0; i < 4; i++) {
        __half2 ha = ((const __half2*)&a)[i];
        __half2 hb = ((const __half2*)&b)[i];
        __half2 he = ((const __half2*)&e)[i];
        float2 fa = __half22float2(ha);
        float2 fb = __half22float2(hb);
        float2 fe = __half22float2(he);
        float s = fa.x + fb.x + fe.x;   // s component
        float g = fa.y + fb.y + fe.y;   // g component
        m[i] = fast_sigmoid(s) * fast_softplus(g);
    }

    float* dp = agg + (size_t)src * 128 + lane * 4;
    asm volatile("red.global.add.v4.f32 [%0], {%1,%2,%3,%4};"
                 :: "l"(dp), "f"(m[0]), "f"(m[1]), "f"(m[2]), "f"(m[3])
                 : "memory");
}

// ---------------------------------------------------------------------------
__global__ void zero_kernel(float* __restrict__ p, int n) {
    int i = blockIdx.x * blockDim.x + threadIdx.x;
    if (i < n) p[i] = 0.0f;
}

__global__ void update_kernel(const float* __restrict__ xin, const float* __restrict__ agg,
                              float* __restrict__ xout, int n) {
    int i = blockIdx.x * blockDim.x + threadIdx.x;
    if (i < n) xout[i] = fast_softplus(xin[i] + agg[i]);
}

// ---------------------------------------------------------------------------
extern "C" void kernel_launch(void* const* d_in, const int* in_sizes, int n_in,
                              void* d_out, int out_size) {
    const float* atom = (const float*)d_in[0];   // [n_nodes, 128]
    const float* esph = (const float*)d_in[1];   // [n_edges, 64]
    const float* ks   = (const float*)d_in[3];   // [320, 128]
    const float* bs   = (const float*)d_in[4];   // [128]
    const float* kg   = (const float*)d_in[5];   // [320, 128]
    const float* bg   = (const float*)d_in[6];   // [128]
    const int*   pair = (const int*)d_in[7];     // [n_edges, 2] int32
    float* out = (float*)d_out;

    const int n_nodes = in_sizes[0] / 128;
    const int n_edges = in_sizes[1] / 64;

    __half *pE, *pP;
    float *pAgg, *pX, *pWn, *pWe, *pBe;
    cudaGetSymbolAddress((void**)&pE, g_E);
    cudaGetSymbolAddress((void**)&pP, g_P);
    cudaGetSymbolAddress((void**)&pAgg, g_agg);
    cudaGetSymbolAddress((void**)&pX, g_x);
    cudaGetSymbolAddress((void**)&pWn, g_Wn);
    cudaGetSymbolAddress((void**)&pWe, g_We);
    cudaGetSymbolAddress((void**)&pBe, g_be);

    // 1. pack weights (interleaved s/g columns)
    repack_kernel<<<256, 256>>>(ks, kg, bs, bg);

    // 2. E = esph @ W_edge + bias   (M=n_edges, N=256, K=64) -> fp16
    {
        dim3 grid(2, (n_edges + 127) / 128);
        sgemm_h<<<grid, 256>>>(esph, pWe, pBe, pE, n_edges, 256, 64);
    }

    const float* xin = atom;
    const int nelem = n_nodes * 128;
    for (int step = 0; step < 3; step++) {
        zero_kernel<<<(nelem + 511) / 512, 512>>>(pAgg, nelem);

        // P = x @ W_node   (M=n_nodes, N=512, K=128) -> fp16
        dim3 gn(4, (n_nodes + 127) / 128);
        sgemm_h<<<gn, 256>>>(xin, pWn, nullptr, pP, n_nodes, 512, 128);

        edge_kernel<<<(n_edges + 7) / 8, 256>>>(pP, pE, pair, pAgg, n_edges);

        float* xout = (step == 2) ? out : pX;
        update_kernel<<<(nelem + 255) / 256, 256>>>(xin, pAgg, xout, nelem);
        xin = pX;
    }
}

// round 3
// speedup vs baseline: 2.6156x; 1.5891x over previous
#include <cuda_runtime.h>
#include <cuda_fp16.h>
#include <cstdint>

// ---------------------------------------------------------------------------
// CrystalGraphConvolution via tensor cores (HMMA mma.sync m16n8k16).
//   P = x @ W_node  (fp16 in/out, fp32 accum)  [n_nodes, 512] interleaved (s,g)
//   E = e @ W_edge + bias (precomputed once)   [n_edges, 256] interleaved (s,g)
//   edge kernel: warp/edge, fused sigmoid*softplus, red.v4 into agg[src]
//   x = softplus(x + agg)
// B matrices are stored pre-swizzled in HMMA fragment order -> GEMM needs no
// smem: B frags = one uint2 load/lane (L1-hot), A frags = 4x b32 loads.
// ---------------------------------------------------------------------------

#define MAX_NODES 50000
#define MAX_EDGES 800000

static __device__ __align__(16) __half g_E[(size_t)MAX_EDGES * 256];   // ~410 MB
static __device__ __align__(16) __half g_eh[(size_t)MAX_EDGES * 64];   // esph fp16
static __device__ __align__(16) __half g_P[(size_t)MAX_NODES * 512];
static __device__ __align__(16) __half g_xh[(size_t)MAX_NODES * 128];
static __device__ float g_agg[(size_t)MAX_NODES * 128];
static __device__ float g_x[(size_t)MAX_NODES * 128];
// B pre-swizzled into mma fragment order (uint = 2 halves {B[k][n], B[k+1][n]})
static __device__ __align__(16) unsigned g_Bn[8 * 64 * 64];   // node: K=128,N=512
static __device__ __align__(16) unsigned g_Be[4 * 32 * 64];   // edge: K=64, N=256
static __device__ float g_be[256];

__device__ __forceinline__ float fast_sigmoid(float x) {
    return __fdividef(1.0f, 1.0f + __expf(-x));
}
__device__ __forceinline__ float fast_softplus(float x) {
    return fmaxf(x, 0.0f) + __logf(1.0f + __expf(-fabsf(x)));
}

// ---------------------------------------------------------------------------
// Logical B with interleaved (s,g) columns.
__device__ __forceinline__ float Bnode(const float* ks, const float* kg, int k, int j) {
    if (j < 256) { int c = j >> 1; return (j & 1) ? kg[k * 128 + c] : ks[k * 128 + c]; }
    int c = (j - 256) >> 1;
    return (j & 1) ? kg[(128 + k) * 128 + c] : ks[(128 + k) * 128 + c];
}
__device__ __forceinline__ float Bedge(const float* ks, const float* kg, int k, int j) {
    int c = j >> 1;
    return (j & 1) ? kg[(256 + k) * 128 + c] : ks[(256 + k) * 128 + c];
}

__device__ __forceinline__ unsigned pack2(float lo, float hi) {
    __half2 h = __floats2half2_rn(lo, hi);
    return *(unsigned*)&h;
}

// Pre-swizzle B into fragment order:
// word(frag, w) : frag = ks*NF + nf ; w in [0,64): lane = w>>1, j = w&1
//   k0 = ks*16 + (lane&3)*2 + j*8 ; n = nf*8 + (lane>>2)
//   value = {B[k0][n], B[k0+1][n]}
__global__ void repack_kernel(const float* __restrict__ ks, const float* __restrict__ kg,
                              const float* __restrict__ bs, const float* __restrict__ bg) {
    int i = blockIdx.x * blockDim.x + threadIdx.x;
    if (i < 8 * 64 * 64) {                       // node
        int w = i & 63, frag = i >> 6;
        int lane = w >> 1, j = w & 1;
        int kstep = frag / 64, nf = frag % 64;
        int k0 = kstep * 16 + (lane & 3) * 2 + j * 8;
        int n = nf * 8 + (lane >> 2);
        g_Bn[(size_t)frag * 64 + lane * 2 + j] =
            pack2(Bnode(ks, kg, k0, n), Bnode(ks, kg, k0 + 1, n));
    }
    if (i < 4 * 32 * 64) {                       // edge
        int w = i & 63, frag = i >> 6;
        int lane = w >> 1, j = w & 1;
        int kstep = frag / 32, nf = frag % 32;
        int k0 = kstep * 16 + (lane & 3) * 2 + j * 8;
        int n = nf * 8 + (lane >> 2);
        g_Be[(size_t)frag * 64 + lane * 2 + j] =
            pack2(Bedge(ks, kg, k0, n), Bedge(ks, kg, k0 + 1, n));
    }
    if (i < 256) {
        int c = i >> 1;
        g_be[i] = (i & 1) ? bg[c] : bs[c];
    }
}

// ---------------------------------------------------------------------------
// HMMA GEMM: C[M,N] = A[M,K] @ B + bias. A fp16 row-major, B pre-swizzled,
// C fp16. 256 threads = 8 warps (2 m x 4 n). Block tile 64m x 256n.
template<int N, int K>
__global__ __launch_bounds__(256) void hgemm(
    const __half* __restrict__ A, const unsigned* __restrict__ Bsw,
    const float* __restrict__ bias, __half* __restrict__ C, int M)
{
    constexpr int NF = N / 8;
    const int w = threadIdx.x >> 5, lane = threadIdx.x & 31;
    const int wm = w & 1, wn = w >> 1;
    const int m0 = blockIdx.y * 64 + wm * 32;
    const int n0 = blockIdx.x * 256 + wn * 64;
    const int g = lane >> 2, q2 = (lane & 3) * 2;
    const int nf0 = n0 >> 3;

    float acc[2][8][4];
#pragma unroll
    for (int i = 0; i < 2; i++)
#pragma unroll
        for (int f = 0; f < 8; f++)
#pragma unroll
            for (int t = 0; t < 4; t++) acc[i][f][t] = 0.0f;

#pragma unroll
    for (int ks = 0; ks < K / 16; ks++) {
        unsigned a[2][4];
#pragma unroll
        for (int i = 0; i < 2; i++) {
            int r = m0 + i * 16 + g;
            bool v0 = r < M, v1 = (r + 8) < M;
            const __half* p0 = A + (size_t)r * K + ks * 16 + q2;
            const __half* p1 = A + (size_t)(r + 8) * K + ks * 16 + q2;
            a[i][0] = v0 ? *(const unsigned*)p0 : 0u;
            a[i][1] = v1 ? *(const unsigned*)p1 : 0u;
            a[i][2] = v0 ? *(const unsigned*)(p0 + 8) : 0u;
            a[i][3] = v1 ? *(const unsigned*)(p1 + 8) : 0u;
        }
#pragma unroll
        for (int f = 0; f < 8; f++) {
            uint2 b = *(const uint2*)(Bsw + (size_t)(ks * NF + nf0 + f) * 64 + lane * 2);
#pragma unroll
            for (int i = 0; i < 2; i++) {
                asm volatile(
                    "mma.sync.aligned.m16n8k16.row.col.f32.f16.f16.f32 "
                    "{%0,%1,%2,%3}, {%4,%5,%6,%7}, {%8,%9}, {%0,%1,%2,%3};"
                    : "+f"(acc[i][f][0]), "+f"(acc[i][f][1]),
                      "+f"(acc[i][f][2]), "+f"(acc[i][f][3])
                    : "r"(a[i][0]), "r"(a[i][1]), "r"(a[i][2]), "r"(a[i][3]),
                      "r"(b.x), "r"(b.y));
            }
        }
    }

#pragma unroll
    for (int i = 0; i < 2; i++) {
        int r = m0 + i * 16 + g;
#pragma unroll
        for (int f = 0; f < 8; f++) {
            int n = n0 + f * 8 + q2;
            float b0 = 0.f, b1 = 0.f;
            if (bias) { b0 = bias[n]; b1 = bias[n + 1]; }
            if (r < M) {
                __half2 h = __floats2half2_rn(acc[i][f][0] + b0, acc[i][f][1] + b1);
                *(__half2*)(C + (size_t)r * N + n) = h;
            }
            if (r + 8 < M) {
                __half2 h = __floats2half2_rn(acc[i][f][2] + b0, acc[i][f][3] + b1);
                *(__half2*)(C + (size_t)(r + 8) * N + n) = h;
            }
        }
    }
}

// ---------------------------------------------------------------------------
// One warp per edge; lane l owns output cols 4l..4l+3.
__global__ __launch_bounds__(256) void edge_kernel(
    const __half* __restrict__ P, const __half* __restrict__ E,
    const int* __restrict__ pair, float* __restrict__ agg, int n_edges)
{
    int gw = (blockIdx.x * blockDim.x + threadIdx.x) >> 5;
    int lane = threadIdx.x & 31;
    if (gw >= n_edges) return;

    int src = pair[2 * gw];
    int dst = pair[2 * gw + 1];

    const uint4* ps = (const uint4*)(P + (size_t)src * 512);
    const uint4* pd = (const uint4*)(P + (size_t)dst * 512 + 256);
    const uint4* ep = (const uint4*)(E + (size_t)gw * 256);

    uint4 a = ps[lane];
    uint4 b = pd[lane];
    uint4 e = ep[lane];

    float m[4];
#pragma unroll
    for (int i = 0; i < 4; i++) {
        float2 fa = __half22float2(((const __half2*)&a)[i]);
        float2 fb = __half22float2(((const __half2*)&b)[i]);
        float2 fe = __half22float2(((const __half2*)&e)[i]);
        float s = fa.x + fb.x + fe.x;
        float gg = fa.y + fb.y + fe.y;
        m[i] = fast_sigmoid(s) * fast_softplus(gg);
    }

    float* dp = agg + (size_t)src * 128 + lane * 4;
    asm volatile("red.global.add.v4.f32 [%0], {%1,%2,%3,%4};"
                 :: "l"(dp), "f"(m[0]), "f"(m[1]), "f"(m[2]), "f"(m[3])
                 : "memory");
}

// ---------------------------------------------------------------------------
__global__ void zero_kernel(float4* __restrict__ p, int n4) {
    int i = blockIdx.x * blockDim.x + threadIdx.x;
    if (i < n4) p[i] = make_float4(0.f, 0.f, 0.f, 0.f);
}

// fp32 -> fp16, 4 elems/thread
__global__ void f2h_kernel(const float4* __restrict__ in, __half* __restrict__ out, int n4) {
    int i = blockIdx.x * blockDim.x + threadIdx.x;
    if (i < n4) {
        float4 v = in[i];
        __half2 h0 = __floats2half2_rn(v.x, v.y);
        __half2 h1 = __floats2half2_rn(v.z, v.w);
        *(uint2*)(out + (size_t)i * 4) = make_uint2(*(unsigned*)&h0, *(unsigned*)&h1);
    }
}

// x' = softplus(x + agg), write fp32 (and fp16 copy for next GEMM)
__global__ void update_kernel(const float* __restrict__ xin, const float* __restrict__ agg,
                              float* __restrict__ xout, __half* __restrict__ xh, int n) {
    int i = blockIdx.x * blockDim.x + threadIdx.x;
    if (i < n) {
        float v = fast_softplus(xin[i] + agg[i]);
        xout[i] = v;
        xh[i] = __float2half(v);
    }
}

// ---------------------------------------------------------------------------
extern "C" void kernel_launch(void* const* d_in, const int* in_sizes, int n_in,
                              void* d_out, int out_size) {
    const float* atom = (const float*)d_in[0];   // [n_nodes, 128]
    const float* esph = (const float*)d_in[1];   // [n_edges, 64]
    const float* ks   = (const float*)d_in[3];   // [320, 128]
    const float* bs   = (const float*)d_in[4];   // [128]
    const float* kg   = (const float*)d_in[5];   // [320, 128]
    const float* bg   = (const float*)d_in[6];   // [128]
    const int*   pair = (const int*)d_in[7];     // [n_edges, 2] int32
    float* out = (float*)d_out;

    const int n_nodes = in_sizes[0] / 128;
    const int n_edges = in_sizes[1] / 64;

    __half *pE, *pP, *pEh, *pXh;
    float *pAgg, *pX, *pBe;
    unsigned *pBn, *pBesw;
    cudaGetSymbolAddress((void**)&pE, g_E);
    cudaGetSymbolAddress((void**)&pP, g_P);
    cudaGetSymbolAddress((void**)&pEh, g_eh);
    cudaGetSymbolAddress((void**)&pXh, g_xh);
    cudaGetSymbolAddress((void**)&pAgg, g_agg);
    cudaGetSymbolAddress((void**)&pX, g_x);
    cudaGetSymbolAddress((void**)&pBn, g_Bn);
    cudaGetSymbolAddress((void**)&pBesw, g_Be);
    cudaGetSymbolAddress((void**)&pBe, g_be);

    // 1. repack weights into fragment-swizzled fp16
    repack_kernel<<<(8 * 64 * 64 + 255) / 256, 256>>>(ks, kg, bs, bg);

    // 2. convert esph -> fp16
    {
        int n4 = n_edges * 64 / 4;
        f2h_kernel<<<(n4 + 255) / 256, 256>>>((const float4*)esph, pEh, n4);
    }

    // 3. E = esph @ W_edge + bias  (M=n_edges, N=256, K=64) -> fp16
    {
        dim3 grid(1, (n_edges + 63) / 64);
        hgemm<256, 64><<<grid, 256>>>(pEh, pBesw, pBe, pE, n_edges);
    }

    // 4. convert atom -> fp16 (step-0 GEMM input)
    {
        int n4 = n_nodes * 128 / 4;
        f2h_kernel<<<(n4 + 255) / 256, 256>>>((const float4*)atom, pXh, n4);
    }

    const float* xin = atom;
    const int nelem = n_nodes * 128;
    for (int step = 0; step < 3; step++) {
        zero_kernel<<<(nelem / 4 + 255) / 256, 256>>>((float4*)pAgg, nelem / 4);

        // P = x @ W_node (M=n_nodes, N=512, K=128) -> fp16
        dim3 gn(2, (n_nodes + 63) / 64);
        hgemm<512, 128><<<gn, 256>>>(pXh, pBn, nullptr, pP, n_nodes);

        edge_kernel<<<(n_edges + 7) / 8, 256>>>(pP, pE, pair, pAgg, n_edges);

        float* xout = (step == 2) ? out : pX;
        update_kernel<<<(nelem + 255) / 256, 256>>>(xin, pAgg, xout, pXh, nelem);
        xin = pX;
    }
}